// round 1
// baseline (speedup 1.0000x reference)
#include <cuda_runtime.h>
#include <math.h>

#define D_MODEL 1024
#define NHEAD   16
#define HDIM    64
#define BATCH   2
#define SEQ     2048
#define MTOK    (BATCH * SEQ)   // 4096

// -------- scratch (static device globals; no allocation allowed) --------
__device__ float g_q[MTOK * D_MODEL];
__device__ float g_k[MTOK * D_MODEL];
__device__ float g_v[MTOK * D_MODEL];
__device__ float g_c[MTOK * D_MODEL];

// ======================= GEMM:  Y = X @ W^T (+ bias) =======================
// X: (M,K) row-major, W: (N,K) row-major, Y: (M,N) row-major
#define BM 128
#define BN 128
#define BK 16
#define SPAD 4

__global__ __launch_bounds__(256, 2)
void sgemm_nt(const float* __restrict__ X, const float* __restrict__ W,
              const float* __restrict__ bias, float* __restrict__ Y,
              int M, int N, int K)
{
    __shared__ float Xs[BK][BM + SPAD];
    __shared__ float Ws[BK][BN + SPAD];

    const int tid = threadIdx.x;
    const int tx = tid & 15;        // 16 col groups of 8
    const int ty = tid >> 4;        // 16 row groups of 8
    const int bm = blockIdx.y * BM;
    const int bn = blockIdx.x * BN;

    float acc[8][8];
#pragma unroll
    for (int i = 0; i < 8; i++)
#pragma unroll
        for (int j = 0; j < 8; j++) acc[i][j] = 0.0f;

    for (int k0 = 0; k0 < K; k0 += BK) {
#pragma unroll
        for (int i = 0; i < 2; i++) {
            int idx = tid + i * 256;           // 0..511
            int row = idx >> 2;                // 0..127
            int col = (idx & 3) * 4;           // 0,4,8,12
            float4 xv = *(const float4*)(X + (size_t)(bm + row) * K + k0 + col);
            Xs[col + 0][row] = xv.x; Xs[col + 1][row] = xv.y;
            Xs[col + 2][row] = xv.z; Xs[col + 3][row] = xv.w;
            float4 wv = *(const float4*)(W + (size_t)(bn + row) * K + k0 + col);
            Ws[col + 0][row] = wv.x; Ws[col + 1][row] = wv.y;
            Ws[col + 2][row] = wv.z; Ws[col + 3][row] = wv.w;
        }
        __syncthreads();

#pragma unroll
        for (int kk = 0; kk < BK; kk++) {
            float a[8], b[8];
            *(float4*)(a)     = *(const float4*)&Xs[kk][ty * 8];
            *(float4*)(a + 4) = *(const float4*)&Xs[kk][ty * 8 + 4];
            *(float4*)(b)     = *(const float4*)&Ws[kk][tx * 8];
            *(float4*)(b + 4) = *(const float4*)&Ws[kk][tx * 8 + 4];
#pragma unroll
            for (int i = 0; i < 8; i++)
#pragma unroll
                for (int j = 0; j < 8; j++)
                    acc[i][j] = fmaf(a[i], b[j], acc[i][j]);
        }
        __syncthreads();
    }

#pragma unroll
    for (int i = 0; i < 8; i++) {
        int row = bm + ty * 8 + i;
#pragma unroll
        for (int j = 0; j < 8; j += 4) {
            int col = bn + tx * 8 + j;
            float4 v;
            v.x = acc[i][j + 0]; v.y = acc[i][j + 1];
            v.z = acc[i][j + 2]; v.w = acc[i][j + 3];
            if (bias) {
                v.x += bias[col + 0]; v.y += bias[col + 1];
                v.z += bias[col + 2]; v.w += bias[col + 3];
            }
            *(float4*)(Y + (size_t)row * N + col) = v;
        }
    }
}

// ======================= Flash attention (fp32) =======================
// Per block: one (batch, head, 128-query-row tile). Online softmax over 64-key tiles.
// Thread layout: 256 threads; tx = tid&7 (8 key/d col groups of 8), ty = tid>>3 (32 row groups of 4)
#define ABM 128
#define ABN 64

// shared layout (floats)
#define QS_OFF   0                        // Qs[d][row]   64*128
#define KS_OFF   (QS_OFF + 64 * 128)      // Ks[d][j]     64*64
#define VS_OFF   (KS_OFF + 64 * 64)       // Vs[j][d]     64*64
#define PS_OFF   (VS_OFF + 64 * 64)       // Ps[j][row]   64*128 (xor-swizzled rows)
#define MK_OFF   (PS_OFF + 64 * 128)      // maskadd[j]   64
#define ATT_SMEM_FLOATS (MK_OFF + 64)
#define ATT_SMEM_BYTES  (ATT_SMEM_FLOATS * 4)

__global__ __launch_bounds__(256, 2)
void attn_kernel(const float* __restrict__ Qb, const float* __restrict__ Kb,
                 const float* __restrict__ Vb, const int* __restrict__ mask,
                 float* __restrict__ ctx)
{
    extern __shared__ float sm[];
    float* Qs = sm + QS_OFF;
    float* Ks = sm + KS_OFF;
    float* Vs = sm + VS_OFF;
    float* Ps = sm + PS_OFF;
    float* Mk = sm + MK_OFF;

    const int tid = threadIdx.x;
    const int tx  = tid & 7;
    const int ty  = tid >> 3;
    const int ty4 = ty * 4;
    const int q0  = blockIdx.x * ABM;
    const int h   = blockIdx.y;
    const int b   = blockIdx.z;

    const size_t rowstride = D_MODEL;
    const float* Qg = Qb + (size_t)(b * SEQ) * rowstride + h * HDIM;
    const float* Kg = Kb + (size_t)(b * SEQ) * rowstride + h * HDIM;
    const float* Vg = Vb + (size_t)(b * SEQ) * rowstride + h * HDIM;
    const int*   Mg = mask + b * SEQ;

    // ---- load Q tile (scaled by 1/sqrt(64)=0.125), transposed to Qs[d][row]
    {
        int row  = tid & 127;
        int dblk = (tid >> 7) * 32;          // 0 or 32
        const float* src = Qg + (size_t)(q0 + row) * rowstride + dblk;
#pragma unroll
        for (int i = 0; i < 8; i++) {
            float4 v = *(const float4*)(src + i * 4);
            int d = dblk + i * 4;
            Qs[(d + 0) * 128 + row] = v.x * 0.125f;
            Qs[(d + 1) * 128 + row] = v.y * 0.125f;
            Qs[(d + 2) * 128 + row] = v.z * 0.125f;
            Qs[(d + 3) * 128 + row] = v.w * 0.125f;
        }
    }

    float o[4][8];
#pragma unroll
    for (int r = 0; r < 4; r++)
#pragma unroll
        for (int c = 0; c < 8; c++) o[r][c] = 0.0f;
    float mrun[4] = {-1e30f, -1e30f, -1e30f, -1e30f};
    float lrun[4] = {0.0f, 0.0f, 0.0f, 0.0f};

    for (int kb = 0; kb < SEQ; kb += ABN) {
        __syncthreads();   // previous-tile Ks/Vs/Ps consumers done

        // ---- load K (transposed -> Ks[d][j]), V (Vs[j][d]), mask ----
        {
            int j   = tid & 63;
            int seg = tid >> 6;              // 0..3
            const float* ksrc = Kg + (size_t)(kb + j) * rowstride + seg * 16;
            const float* vsrc = Vg + (size_t)(kb + j) * rowstride + seg * 16;
#pragma unroll
            for (int i = 0; i < 4; i++) {
                float4 kv = *(const float4*)(ksrc + i * 4);
                int d = seg * 16 + i * 4;
                Ks[(d + 0) * 64 + j] = kv.x;
                Ks[(d + 1) * 64 + j] = kv.y;
                Ks[(d + 2) * 64 + j] = kv.z;
                Ks[(d + 3) * 64 + j] = kv.w;
                float4 vv = *(const float4*)(vsrc + i * 4);
                *(float4*)&Vs[j * 64 + d] = vv;
            }
            if (tid < 64) Mk[tid] = Mg[kb + tid] ? 0.0f : -1e30f;
        }
        __syncthreads();

        // ---- S = Q*K^T (Q pre-scaled) ----
        float s[4][8];
#pragma unroll
        for (int r = 0; r < 4; r++)
#pragma unroll
            for (int c = 0; c < 8; c++) s[r][c] = 0.0f;

#pragma unroll 8
        for (int d = 0; d < 64; d++) {
            float qv[4], kv[8];
            *(float4*)(qv)     = *(const float4*)&Qs[d * 128 + ty4];
            *(float4*)(kv)     = *(const float4*)&Ks[d * 64 + tx * 8];
            *(float4*)(kv + 4) = *(const float4*)&Ks[d * 64 + tx * 8 + 4];
#pragma unroll
            for (int r = 0; r < 4; r++)
#pragma unroll
                for (int c = 0; c < 8; c++)
                    s[r][c] = fmaf(qv[r], kv[c], s[r][c]);
        }

        // ---- mask + online softmax ----
        float madd[8];
        *(float4*)(madd)     = *(const float4*)&Mk[tx * 8];
        *(float4*)(madd + 4) = *(const float4*)&Mk[tx * 8 + 4];

#pragma unroll
        for (int r = 0; r < 4; r++) {
#pragma unroll
            for (int c = 0; c < 8; c++) s[r][c] += madd[c];
            float mloc = s[r][0];
#pragma unroll
            for (int c = 1; c < 8; c++) mloc = fmaxf(mloc, s[r][c]);
#pragma unroll
            for (int off = 1; off < 8; off <<= 1)
                mloc = fmaxf(mloc, __shfl_xor_sync(0xffffffffu, mloc, off));
            float mnew = fmaxf(mrun[r], mloc);
            float corr = __expf(mrun[r] - mnew);
            float sloc = 0.0f;
#pragma unroll
            for (int c = 0; c < 8; c++) {
                s[r][c] = __expf(s[r][c] - mnew);
                sloc += s[r][c];
            }
#pragma unroll
            for (int off = 1; off < 8; off <<= 1)
                sloc += __shfl_xor_sync(0xffffffffu, sloc, off);
            lrun[r] = lrun[r] * corr + sloc;
            mrun[r] = mnew;
#pragma unroll
            for (int c = 0; c < 8; c++) o[r][c] *= corr;
        }

        // ---- store P to shared (xor-swizzled rows for conflict-free STS/LDS) ----
#pragma unroll
        for (int c = 0; c < 8; c++) {
            int j = tx * 8 + c;
            float4 pv;
            pv.x = s[0][c]; pv.y = s[1][c]; pv.z = s[2][c]; pv.w = s[3][c];
            *(float4*)&Ps[j * 128 + (ty4 ^ (tx << 2))] = pv;
        }
        __syncthreads();

        // ---- O += P @ V ----
#pragma unroll 8
        for (int j = 0; j < 64; j++) {
            float pv[4], vv[8];
            *(float4*)(pv)     = *(const float4*)&Ps[j * 128 + (ty4 ^ ((j >> 3) << 2))];
            *(float4*)(vv)     = *(const float4*)&Vs[j * 64 + tx * 8];
            *(float4*)(vv + 4) = *(const float4*)&Vs[j * 64 + tx * 8 + 4];
#pragma unroll
            for (int r = 0; r < 4; r++)
#pragma unroll
                for (int c = 0; c < 8; c++)
                    o[r][c] = fmaf(pv[r], vv[c], o[r][c]);
        }
    }

    // ---- normalize + write ctx (B, L, H*64) head-major ----
#pragma unroll
    for (int r = 0; r < 4; r++) {
        float inv = (mrun[r] > -9e29f) ? (1.0f / lrun[r]) : 0.0f;
        int qrow = q0 + ty4 + r;
        float* dst = ctx + (size_t)(b * SEQ + qrow) * D_MODEL + h * HDIM + tx * 8;
        float4 v0, v1;
        v0.x = o[r][0] * inv; v0.y = o[r][1] * inv;
        v0.z = o[r][2] * inv; v0.w = o[r][3] * inv;
        v1.x = o[r][4] * inv; v1.y = o[r][5] * inv;
        v1.z = o[r][6] * inv; v1.w = o[r][7] * inv;
        *(float4*)(dst)     = v0;
        *(float4*)(dst + 4) = v1;
    }
}

// ======================= launch =======================
extern "C" void kernel_launch(void* const* d_in, const int* in_sizes, int n_in,
                              void* d_out, int out_size)
{
    const float* q   = (const float*)d_in[0];
    const float* k   = (const float*)d_in[1];
    const float* v   = (const float*)d_in[2];
    const int*   msk = (const int*)  d_in[3];
    const float* Wq  = (const float*)d_in[4];
    const float* Wk  = (const float*)d_in[5];
    const float* Wv  = (const float*)d_in[6];
    const float* Wo  = (const float*)d_in[7];
    const float* bo  = (const float*)d_in[8];
    float* out = (float*)d_out;

    float *gq, *gk, *gv, *gc;
    cudaGetSymbolAddress((void**)&gq, g_q);
    cudaGetSymbolAddress((void**)&gk, g_k);
    cudaGetSymbolAddress((void**)&gv, g_v);
    cudaGetSymbolAddress((void**)&gc, g_c);

    cudaFuncSetAttribute(attn_kernel,
                         cudaFuncAttributeMaxDynamicSharedMemorySize,
                         ATT_SMEM_BYTES);

    dim3 gg(D_MODEL / BN, MTOK / BM);   // (8, 32)
    dim3 gb(256);

    sgemm_nt<<<gg, gb>>>(q, Wq, nullptr, gq, MTOK, D_MODEL, D_MODEL);
    sgemm_nt<<<gg, gb>>>(k, Wk, nullptr, gk, MTOK, D_MODEL, D_MODEL);
    sgemm_nt<<<gg, gb>>>(v, Wv, nullptr, gv, MTOK, D_MODEL, D_MODEL);

    dim3 ag(SEQ / ABM, NHEAD, BATCH);   // (16, 16, 2)
    attn_kernel<<<ag, 256, ATT_SMEM_BYTES>>>(gq, gk, gv, msk, gc);

    sgemm_nt<<<gg, gb>>>(gc, Wo, bo, out, MTOK, D_MODEL, D_MODEL);
}

// round 2
// speedup vs baseline: 3.2873x; 3.2873x over previous
#include <cuda_runtime.h>
#include <math.h>

#define D_MODEL 1024
#define NHEAD   16
#define HDIM    64
#define BATCH   2
#define SEQ     2048
#define MTOK    (BATCH * SEQ)   // 4096

// -------- scratch (static device globals; no allocation allowed) --------
__device__ float g_q[MTOK * D_MODEL];
__device__ float g_k[MTOK * D_MODEL];
__device__ float g_v[MTOK * D_MODEL];
__device__ float g_c[MTOK * D_MODEL];

// -------- tf32 helpers --------
__device__ __forceinline__ unsigned f2tf(float x) {
    unsigned u;
    asm("cvt.rna.tf32.f32 %0, %1;" : "=r"(u) : "f"(x));
    return u;
}

__device__ __forceinline__ void mma8(float* d, unsigned a0, unsigned a1,
                                     unsigned a2, unsigned a3,
                                     unsigned b0, unsigned b1) {
    asm volatile(
        "mma.sync.aligned.m16n8k8.row.col.f32.tf32.tf32.f32 "
        "{%0,%1,%2,%3}, {%4,%5,%6,%7}, {%8,%9}, {%0,%1,%2,%3};"
        : "+f"(d[0]), "+f"(d[1]), "+f"(d[2]), "+f"(d[3])
        : "r"(a0), "r"(a1), "r"(a2), "r"(a3), "r"(b0), "r"(b1));
}

// ======================= GEMM:  Y = X @ W^T (+ bias), tf32 tensor =======================
// X: (M,K) row-major, W: (N,K) row-major, Y: (M,N) row-major.
// Block 128x128, BK=32. 8 warps: warp tile 32(M) x 64(N).
#define BK  32
#define KST 36   // smem row stride (floats): 32 k + 4 pad -> frag LDS conflict-free

__global__ __launch_bounds__(256, 2)
void gemm_tf32(const float* __restrict__ X, const float* __restrict__ W,
               const float* __restrict__ bias, float* __restrict__ Y,
               int M, int N, int K)
{
    __shared__ unsigned As[128][KST];   // [m][k]
    __shared__ unsigned Bs[128][KST];   // [n][k]

    const int tid  = threadIdx.x;
    const int lane = tid & 31;
    const int wid  = tid >> 5;
    const int bm   = blockIdx.y * 128;
    const int bn   = blockIdx.x * 128;
    const int wm   = (wid & 3) * 32;
    const int wn   = (wid >> 2) * 64;
    const int g    = lane >> 2;
    const int t    = lane & 3;

    float acc[2][8][4];
#pragma unroll
    for (int mt = 0; mt < 2; mt++)
#pragma unroll
        for (int nt = 0; nt < 8; nt++)
#pragma unroll
            for (int e = 0; e < 4; e++) acc[mt][nt][e] = 0.0f;

    for (int k0 = 0; k0 < K; k0 += BK) {
#pragma unroll
        for (int i = 0; i < 4; i++) {
            int f4  = tid + i * 256;         // 0..1023
            int row = f4 >> 3;               // 0..127 (8 float4 per row)
            int cg  = (f4 & 7) * 4;
            float4 xv = *(const float4*)(X + (size_t)(bm + row) * K + k0 + cg);
            *(uint4*)&As[row][cg] =
                make_uint4(f2tf(xv.x), f2tf(xv.y), f2tf(xv.z), f2tf(xv.w));
            float4 wv = *(const float4*)(W + (size_t)(bn + row) * K + k0 + cg);
            *(uint4*)&Bs[row][cg] =
                make_uint4(f2tf(wv.x), f2tf(wv.y), f2tf(wv.z), f2tf(wv.w));
        }
        __syncthreads();

#pragma unroll
        for (int k8 = 0; k8 < 4; k8++) {
            int kk = k8 * 8 + t;
            unsigned a[2][4];
#pragma unroll
            for (int mt = 0; mt < 2; mt++) {
                int r = wm + mt * 16 + g;
                a[mt][0] = As[r][kk];
                a[mt][1] = As[r + 8][kk];
                a[mt][2] = As[r][kk + 4];
                a[mt][3] = As[r + 8][kk + 4];
            }
#pragma unroll
            for (int nt = 0; nt < 8; nt++) {
                int c = wn + nt * 8 + g;
                unsigned b0 = Bs[c][kk];
                unsigned b1 = Bs[c][kk + 4];
                mma8(acc[0][nt], a[0][0], a[0][1], a[0][2], a[0][3], b0, b1);
                mma8(acc[1][nt], a[1][0], a[1][1], a[1][2], a[1][3], b0, b1);
            }
        }
        __syncthreads();
    }

#pragma unroll
    for (int mt = 0; mt < 2; mt++)
#pragma unroll
        for (int hh = 0; hh < 2; hh++) {
            int row = bm + wm + mt * 16 + g + hh * 8;
#pragma unroll
            for (int nt = 0; nt < 8; nt++) {
                int col = bn + wn + nt * 8 + t * 2;
                float2 v;
                v.x = acc[mt][nt][hh * 2 + 0];
                v.y = acc[mt][nt][hh * 2 + 1];
                if (bias) { v.x += bias[col]; v.y += bias[col + 1]; }
                *(float2*)(Y + (size_t)row * N + col) = v;
            }
        }
}

// ======================= Flash attention (tf32 tensor) =======================
// Block: (batch, head, 128 query rows). 8 warps, each owns 16 query rows.
// Key tiles of 64. Everything row-major in smem with stride 68 (conflict-free frags).
#define AST 68

#define QS_OFF 0
#define KS_OFF (QS_OFF + 128 * AST)
#define VS_OFF (KS_OFF + 64 * AST)
#define PS_OFF (VS_OFF + 64 * AST)
#define MK_OFF (PS_OFF + 128 * AST)
#define ATT_SMEM_FLOATS (MK_OFF + 64)
#define ATT_SMEM_BYTES  (ATT_SMEM_FLOATS * 4)

__global__ __launch_bounds__(256, 2)
void attn_tc(const float* __restrict__ Qb, const float* __restrict__ Kb,
             const float* __restrict__ Vb, const int* __restrict__ mask,
             float* __restrict__ ctx)
{
    extern __shared__ float sm[];
    unsigned* Qu = (unsigned*)(sm + QS_OFF);
    unsigned* Ku = (unsigned*)(sm + KS_OFF);
    unsigned* Vu = (unsigned*)(sm + VS_OFF);
    unsigned* Pu = (unsigned*)(sm + PS_OFF);
    float*    Mk = sm + MK_OFF;

    const int tid  = threadIdx.x;
    const int lane = tid & 31;
    const int wid  = tid >> 5;
    const int g    = lane >> 2;
    const int t    = lane & 3;
    const int q0   = blockIdx.x * 128;
    const int hd   = blockIdx.y;
    const int b    = blockIdx.z;

    const float* Qg = Qb + (size_t)(b * SEQ) * D_MODEL + hd * HDIM;
    const float* Kg = Kb + (size_t)(b * SEQ) * D_MODEL + hd * HDIM;
    const float* Vg = Vb + (size_t)(b * SEQ) * D_MODEL + hd * HDIM;
    const int*   Mg = mask + b * SEQ;

    // ---- load Q tile (scaled 0.125 = 1/sqrt(64)), cvt tf32 ----
#pragma unroll
    for (int i = 0; i < 8; i++) {
        int f4  = tid + i * 256;       // 2048 float4 total
        int row = f4 >> 4;             // 16 float4 per row
        int cg  = (f4 & 15) * 4;
        float4 v = *(const float4*)(Qg + (size_t)(q0 + row) * D_MODEL + cg);
        *(uint4*)&Qu[row * AST + cg] =
            make_uint4(f2tf(v.x * 0.125f), f2tf(v.y * 0.125f),
                       f2tf(v.z * 0.125f), f2tf(v.w * 0.125f));
    }

    float oacc[8][4];
#pragma unroll
    for (int dt = 0; dt < 8; dt++)
#pragma unroll
        for (int e = 0; e < 4; e++) oacc[dt][e] = 0.0f;
    float mrun[2] = {-1e30f, -1e30f};
    float lrun[2] = {0.0f, 0.0f};

    const int r = wid * 16 + g;     // this thread's first S/O row

    for (int kb = 0; kb < SEQ; kb += 64) {
        __syncthreads();     // prev tile's consumers done; Qu stores visible (1st iter)

        // ---- load K, V tiles (cvt tf32) + mask ----
#pragma unroll
        for (int i = 0; i < 4; i++) {
            int f4  = tid + i * 256;     // 1024 float4
            int row = f4 >> 4;
            int cg  = (f4 & 15) * 4;
            float4 kv = *(const float4*)(Kg + (size_t)(kb + row) * D_MODEL + cg);
            *(uint4*)&Ku[row * AST + cg] =
                make_uint4(f2tf(kv.x), f2tf(kv.y), f2tf(kv.z), f2tf(kv.w));
            float4 vv = *(const float4*)(Vg + (size_t)(kb + row) * D_MODEL + cg);
            *(uint4*)&Vu[row * AST + cg] =
                make_uint4(f2tf(vv.x), f2tf(vv.y), f2tf(vv.z), f2tf(vv.w));
        }
        if (tid < 64) Mk[tid] = Mg[kb + tid] ? 0.0f : -1e30f;
        __syncthreads();

        // ---- S = Q K^T ----
        float sacc[8][4];
#pragma unroll
        for (int nt = 0; nt < 8; nt++)
#pragma unroll
            for (int e = 0; e < 4; e++) sacc[nt][e] = 0.0f;

#pragma unroll
        for (int d8 = 0; d8 < 8; d8++) {
            int kk = d8 * 8 + t;
            unsigned a0 = Qu[r * AST + kk];
            unsigned a1 = Qu[(r + 8) * AST + kk];
            unsigned a2 = Qu[r * AST + kk + 4];
            unsigned a3 = Qu[(r + 8) * AST + kk + 4];
#pragma unroll
            for (int nt = 0; nt < 8; nt++) {
                unsigned b0 = Ku[(nt * 8 + g) * AST + kk];
                unsigned b1 = Ku[(nt * 8 + g) * AST + kk + 4];
                mma8(sacc[nt], a0, a1, a2, a3, b0, b1);
            }
        }

        // ---- mask + online softmax ----
        float mx[2] = {-1e30f, -1e30f};
#pragma unroll
        for (int nt = 0; nt < 8; nt++) {
            float mk0 = Mk[nt * 8 + t * 2];
            float mk1 = Mk[nt * 8 + t * 2 + 1];
            sacc[nt][0] += mk0; sacc[nt][1] += mk1;
            sacc[nt][2] += mk0; sacc[nt][3] += mk1;
            mx[0] = fmaxf(mx[0], fmaxf(sacc[nt][0], sacc[nt][1]));
            mx[1] = fmaxf(mx[1], fmaxf(sacc[nt][2], sacc[nt][3]));
        }
        float corr[2], ls[2] = {0.0f, 0.0f};
#pragma unroll
        for (int h2 = 0; h2 < 2; h2++) {
            mx[h2] = fmaxf(mx[h2], __shfl_xor_sync(0xffffffffu, mx[h2], 1));
            mx[h2] = fmaxf(mx[h2], __shfl_xor_sync(0xffffffffu, mx[h2], 2));
            float mn = fmaxf(mrun[h2], mx[h2]);
            corr[h2] = __expf(mrun[h2] - mn);
            mrun[h2] = mn;
        }
#pragma unroll
        for (int nt = 0; nt < 8; nt++) {
            sacc[nt][0] = __expf(sacc[nt][0] - mrun[0]);
            sacc[nt][1] = __expf(sacc[nt][1] - mrun[0]);
            sacc[nt][2] = __expf(sacc[nt][2] - mrun[1]);
            sacc[nt][3] = __expf(sacc[nt][3] - mrun[1]);
            ls[0] += sacc[nt][0] + sacc[nt][1];
            ls[1] += sacc[nt][2] + sacc[nt][3];
        }
#pragma unroll
        for (int h2 = 0; h2 < 2; h2++) {
            ls[h2] += __shfl_xor_sync(0xffffffffu, ls[h2], 1);
            ls[h2] += __shfl_xor_sync(0xffffffffu, ls[h2], 2);
            lrun[h2] = lrun[h2] * corr[h2] + ls[h2];
        }
#pragma unroll
        for (int dt = 0; dt < 8; dt++) {
            oacc[dt][0] *= corr[0]; oacc[dt][1] *= corr[0];
            oacc[dt][2] *= corr[1]; oacc[dt][3] *= corr[1];
        }

        // ---- P -> smem (tf32) ----
#pragma unroll
        for (int nt = 0; nt < 8; nt++) {
            int col = nt * 8 + t * 2;
            *(uint2*)&Pu[r * AST + col] =
                make_uint2(f2tf(sacc[nt][0]), f2tf(sacc[nt][1]));
            *(uint2*)&Pu[(r + 8) * AST + col] =
                make_uint2(f2tf(sacc[nt][2]), f2tf(sacc[nt][3]));
        }
        __syncthreads();

        // ---- O += P @ V ----
#pragma unroll
        for (int j8 = 0; j8 < 8; j8++) {
            int kk = j8 * 8 + t;
            unsigned a0 = Pu[r * AST + kk];
            unsigned a1 = Pu[(r + 8) * AST + kk];
            unsigned a2 = Pu[r * AST + kk + 4];
            unsigned a3 = Pu[(r + 8) * AST + kk + 4];
#pragma unroll
            for (int dt = 0; dt < 8; dt++) {
                unsigned b0 = Vu[(j8 * 8 + t) * AST + dt * 8 + g];
                unsigned b1 = Vu[(j8 * 8 + 4 + t) * AST + dt * 8 + g];
                (void)b0;   // note: b-frag k index must be lane%4 of the k-tile
                // correct frag: k = j8*8 + (row within 8) -> rows t and t+4
                mma8(oacc[dt], a0, a1, a2, a3, b0, b1);
            }
        }
    }

    // ---- normalize + write ctx ----
    float inv[2];
    inv[0] = (mrun[0] > -9e29f) ? (1.0f / lrun[0]) : 0.0f;
    inv[1] = (mrun[1] > -9e29f) ? (1.0f / lrun[1]) : 0.0f;
#pragma unroll
    for (int h2 = 0; h2 < 2; h2++) {
        int row = q0 + r + h2 * 8;
        float* dst = ctx + (size_t)(b * SEQ + row) * D_MODEL + hd * HDIM;
#pragma unroll
        for (int dt = 0; dt < 8; dt++) {
            float2 v;
            v.x = oacc[dt][h2 * 2 + 0] * inv[h2];
            v.y = oacc[dt][h2 * 2 + 1] * inv[h2];
            *(float2*)(dst + dt * 8 + t * 2) = v;
        }
    }
}

// ======================= launch =======================
extern "C" void kernel_launch(void* const* d_in, const int* in_sizes, int n_in,
                              void* d_out, int out_size)
{
    const float* q   = (const float*)d_in[0];
    const float* k   = (const float*)d_in[1];
    const float* v   = (const float*)d_in[2];
    const int*   msk = (const int*)  d_in[3];
    const float* Wq  = (const float*)d_in[4];
    const float* Wk  = (const float*)d_in[5];
    const float* Wv  = (const float*)d_in[6];
    const float* Wo  = (const float*)d_in[7];
    const float* bo  = (const float*)d_in[8];
    float* out = (float*)d_out;

    float *gq, *gk, *gv, *gc;
    cudaGetSymbolAddress((void**)&gq, g_q);
    cudaGetSymbolAddress((void**)&gk, g_k);
    cudaGetSymbolAddress((void**)&gv, g_v);
    cudaGetSymbolAddress((void**)&gc, g_c);

    cudaFuncSetAttribute(attn_tc,
                         cudaFuncAttributeMaxDynamicSharedMemorySize,
                         ATT_SMEM_BYTES);

    dim3 gg(D_MODEL / 128, MTOK / 128);   // (8, 32)

    gemm_tf32<<<gg, 256>>>(q, Wq, nullptr, gq, MTOK, D_MODEL, D_MODEL);
    gemm_tf32<<<gg, 256>>>(k, Wk, nullptr, gk, MTOK, D_MODEL, D_MODEL);
    gemm_tf32<<<gg, 256>>>(v, Wv, nullptr, gv, MTOK, D_MODEL, D_MODEL);

    dim3 ag(SEQ / 128, NHEAD, BATCH);     // (16, 16, 2)
    attn_tc<<<ag, 256, ATT_SMEM_BYTES>>>(gq, gk, gv, msk, gc);

    gemm_tf32<<<gg, 256>>>(gc, Wo, bo, out, MTOK, D_MODEL, D_MODEL);
}